// round 1
// baseline (speedup 1.0000x reference)
#include <cuda_runtime.h>
#include <math.h>

#define E_EDGES 640000
#define N_NODES 10000
#define D 128
#define H 4
#define NCOMB 1024   // 512 (A, att half) + 512 (U, p half)

// ---------------- scratch (static device globals; no runtime alloc) --------
__device__ float    g_Wcomb[NCOMB * D];          // 512 KB
__device__ float    g_W2T[D * D];                // 64 KB  (W2 transposed: [i][j])
__device__ float    g_Y[(size_t)E_EDGES * NCOMB];// 2.62 GB
__device__ float    g_att[E_EDGES * H];          // 10.2 MB (att logits, then exp)
__device__ unsigned g_m[N_NODES * H];            // encoded segment max
__device__ float    g_s[N_NODES * H];            // segment sum

// monotone float<->uint encoding for atomicMax on signed floats
__device__ __forceinline__ unsigned encodeF(float x) {
    unsigned u = __float_as_uint(x);
    return (u & 0x80000000u) ? ~u : (u | 0x80000000u);
}
__device__ __forceinline__ float decodeF(unsigned e) {
    unsigned u = (e & 0x80000000u) ? (e ^ 0x80000000u) : ~e;
    return __uint_as_float(u);
}

// ---------------- K0: build combined weights + W2^T ------------------------
// blocks 0..511:   Wcomb[h*128+g][f]     = A_h[f][g] = sum_d Wq[h,d,f]*Wk[h,d,g]
// blocks 512..1023 Wcomb[512+h*128+i][f] = U_h[i][f] = sum_d W1[i,d]*Wv[h,d,f]
// blocks 1024..1151: W2T[i][j] = W2[j][i]
__global__ void k_build(const float* __restrict__ Wq, const float* __restrict__ Wk,
                        const float* __restrict__ Wv, const float* __restrict__ W1,
                        const float* __restrict__ W2) {
    int n = blockIdx.x;
    int f = threadIdx.x;
    if (n < NCOMB) {
        float acc = 0.f;
        if (n < H * D) {
            int h = n >> 7, g = n & 127;
            const float* wq = Wq + h * D * D;
            const float* wk = Wk + h * D * D;
            for (int d = 0; d < D; d++) acc += wq[d * D + f] * wk[d * D + g];
        } else {
            int m2 = n - H * D;
            int h = m2 >> 7, i = m2 & 127;
            const float* wv = Wv + h * D * D;
            for (int d = 0; d < D; d++) acc += W1[i * D + d] * wv[d * D + f];
        }
        g_Wcomb[n * D + f] = acc;
    } else {
        int i = n - NCOMB;                 // 0..127
        g_W2T[i * D + f] = W2[f * D + i];
    }
}

// ---------------- K1: reset segment buffers (every call) -------------------
__global__ void k_init() {
    int i = blockIdx.x * 256 + threadIdx.x;
    if (i < N_NODES * H) { g_m[i] = 0u; g_s[i] = 0.f; }
}

// ---------------- K2: Y = Z @ Wcomb^T   (640000 x 1024 x 128) --------------
// tile: 128(M) x 64(N) x 32(K); 256 threads; micro 8m x 4n
__global__ void __launch_bounds__(256) k_gemm(const float* __restrict__ Z) {
    __shared__ float Zs[128][33];
    __shared__ float Ws[64][33];
    const int ntile = blockIdx.x;          // x fastest -> N-tiles of same M-tile co-scheduled (Z reuse in L2)
    const int mtile = blockIdx.y;
    const int e0 = mtile * 128;
    const int n0g = ntile * 64;
    const int tid = threadIdx.x;
    const int tx = tid & 15, ty = tid >> 4;
    const int m0 = ty * 8, n0 = tx * 4;

    float acc[8][4];
#pragma unroll
    for (int i = 0; i < 8; i++)
#pragma unroll
        for (int j = 0; j < 4; j++) acc[i][j] = 0.f;

    for (int kt = 0; kt < 4; kt++) {
        const int kbase = kt * 32;
#pragma unroll
        for (int p = 0; p < 4; p++) {      // Zs: 128x32
            int r = (tid >> 3) + p * 32;
            int q = (tid & 7) * 4;
            float4 v = *(const float4*)&Z[(size_t)(e0 + r) * D + kbase + q];
            Zs[r][q + 0] = v.x; Zs[r][q + 1] = v.y; Zs[r][q + 2] = v.z; Zs[r][q + 3] = v.w;
        }
#pragma unroll
        for (int p = 0; p < 2; p++) {      // Ws: 64x32
            int r = (tid >> 3) + p * 32;
            int q = (tid & 7) * 4;
            float4 v = *(const float4*)&g_Wcomb[(n0g + r) * D + kbase + q];
            Ws[r][q + 0] = v.x; Ws[r][q + 1] = v.y; Ws[r][q + 2] = v.z; Ws[r][q + 3] = v.w;
        }
        __syncthreads();
#pragma unroll
        for (int k = 0; k < 32; k++) {
            float a[8], b[4];
#pragma unroll
            for (int i = 0; i < 8; i++) a[i] = Zs[m0 + i][k];
#pragma unroll
            for (int j = 0; j < 4; j++) b[j] = Ws[n0 + j][k];
#pragma unroll
            for (int i = 0; i < 8; i++)
#pragma unroll
                for (int j = 0; j < 4; j++) acc[i][j] += a[i] * b[j];
        }
        __syncthreads();
    }
#pragma unroll
    for (int i = 0; i < 8; i++) {
        float4 v = make_float4(acc[i][0], acc[i][1], acc[i][2], acc[i][3]);
        *(float4*)&g_Y[(size_t)(e0 + m0 + i) * NCOMB + n0g + n0] = v;
    }
}

// ---------------- K3: att[e,h] = scale * dot(Y[e, h*128: ], Z[e]); seg max -
__global__ void __launch_bounds__(256) k_att(const float* __restrict__ Z,
                                             const int* __restrict__ row) {
    const float scale = 0.08838834764831845f;  // 1/sqrt(128)
    int warp = threadIdx.x >> 5, lane = threadIdx.x & 31;
    int e = blockIdx.x * 8 + warp;
    const float* zp = Z + (size_t)e * D;
    float zv[4];
#pragma unroll
    for (int r = 0; r < 4; r++) zv[r] = zp[r * 32 + lane];
    const float* yp = g_Y + (size_t)e * NCOMB;
    int rw = row[e];
#pragma unroll
    for (int h = 0; h < H; h++) {
        float s = 0.f;
#pragma unroll
        for (int r = 0; r < 4; r++) s += yp[h * 128 + r * 32 + lane] * zv[r];
#pragma unroll
        for (int off = 16; off; off >>= 1) s += __shfl_xor_sync(0xFFFFFFFFu, s, off);
        if (lane == 0) {
            s *= scale;
            g_att[e * H + h] = s;
            atomicMax(&g_m[rw * H + h], encodeF(s));
        }
    }
}

// ---------------- K4: e = exp(att - m[row]); seg sum -----------------------
__global__ void k_exp(const int* __restrict__ row) {
    int i = blockIdx.x * 256 + threadIdx.x;
    if (i >= E_EDGES * H) return;
    int e = i >> 2, h = i & 3;
    int rw = row[e];
    float m = decodeF(g_m[rw * H + h]);
    float ev = __expf(g_att[i] - m);
    g_att[i] = ev;
    atomicAdd(&g_s[rw * H + h], ev);
}

// ---------------- K5: w -> pre -> SiLU -> @W2^T -> out ---------------------
// block: 64 edges; 256 threads; GEMM micro 4m x 8n over K=128 in 4 chunks of 32
__global__ void __launch_bounds__(256) k_final(const int* __restrict__ row,
                                               const float* __restrict__ b1,
                                               const float* __restrict__ b2,
                                               float* __restrict__ out) {
    __shared__ float ws[64][4];
    __shared__ float h1c[64][33];
    __shared__ float W2c[32][128];
    const int e0 = blockIdx.x * 64;
    const int tid = threadIdx.x;

    {   // softmax weights for this tile: 64 edges x 4 heads
        int m = tid >> 2, h = tid & 3;
        int e = e0 + m;
        int rw = row[e];
        ws[m][h] = g_att[e * H + h] / g_s[rw * H + h];
    }

    const int tx = tid & 15, ty = tid >> 4;
    const int n0 = tx * 8, m0 = ty * 4;
    float acc[4][8];
#pragma unroll
    for (int i = 0; i < 4; i++)
#pragma unroll
        for (int j = 0; j < 8; j++) acc[i][j] = 0.f;

    for (int kt = 0; kt < 4; kt++) {
        __syncthreads();                    // ws ready (kt=0); prev k-loop reads done (kt>0)
        // h1 chunk: i in [kt*32, kt*32+32)
#pragma unroll
        for (int r = 0; r < 8; r++) {
            int idx = r * 256 + tid;        // 64*32 = 2048 elements
            int m = idx >> 5, ic = idx & 31;
            int i = kt * 32 + ic;
            const float* yp = g_Y + (size_t)(e0 + m) * NCOMB + 512 + i;
            float pre = b1[i];
#pragma unroll
            for (int h = 0; h < H; h++) pre += ws[m][h] * yp[h * 128];
            h1c[m][ic] = pre / (1.f + __expf(-pre));   // SiLU
        }
        // W2T chunk: rows kt*32 .. kt*32+31 (32x128)
#pragma unroll
        for (int p = 0; p < 4; p++) {
            int r = (tid >> 5) + p * 8;
            int c = (tid & 31) * 4;
            float4 v = *(const float4*)&g_W2T[(kt * 32 + r) * D + c];
            *(float4*)&W2c[r][c] = v;
        }
        __syncthreads();
#pragma unroll
        for (int k = 0; k < 32; k++) {
            float a[4];
#pragma unroll
            for (int mi = 0; mi < 4; mi++) a[mi] = h1c[m0 + mi][k];
            float4 bv0 = *(const float4*)&W2c[k][n0];
            float4 bv1 = *(const float4*)&W2c[k][n0 + 4];
            float b[8] = {bv0.x, bv0.y, bv0.z, bv0.w, bv1.x, bv1.y, bv1.z, bv1.w};
#pragma unroll
            for (int mi = 0; mi < 4; mi++)
#pragma unroll
                for (int j = 0; j < 8; j++) acc[mi][j] += a[mi] * b[j];
        }
    }
    float bb[8];
#pragma unroll
    for (int j = 0; j < 8; j++) bb[j] = b2[n0 + j];
#pragma unroll
    for (int mi = 0; mi < 4; mi++) {
        int e = e0 + m0 + mi;
        float4 o0 = make_float4(acc[mi][0] + bb[0], acc[mi][1] + bb[1],
                                acc[mi][2] + bb[2], acc[mi][3] + bb[3]);
        float4 o1 = make_float4(acc[mi][4] + bb[4], acc[mi][5] + bb[5],
                                acc[mi][6] + bb[6], acc[mi][7] + bb[7]);
        *(float4*)&out[(size_t)e * D + n0] = o0;
        *(float4*)&out[(size_t)e * D + n0 + 4] = o1;
    }
}

// ---------------- launch ----------------------------------------------------
extern "C" void kernel_launch(void* const* d_in, const int* in_sizes, int n_in,
                              void* d_out, int out_size) {
    const float* Z     = (const float*)d_in[0];
    const int*   edges = (const int*)  d_in[1];   // edges[0][:] = row
    const float* Wq    = (const float*)d_in[2];
    const float* Wk    = (const float*)d_in[3];
    const float* Wv    = (const float*)d_in[4];
    const float* W1    = (const float*)d_in[5];
    const float* b1    = (const float*)d_in[6];
    const float* W2    = (const float*)d_in[7];
    const float* b2    = (const float*)d_in[8];
    float* out = (float*)d_out;
    const int* row = edges;  // first E entries of edges

    k_build<<<NCOMB + D, D>>>(Wq, Wk, Wv, W1, W2);
    k_init<<<(N_NODES * H + 255) / 256, 256>>>();
    k_gemm<<<dim3(NCOMB / 64, E_EDGES / 128), 256>>>(Z);
    k_att<<<E_EDGES / 8, 256>>>(Z, row);
    k_exp<<<(E_EDGES * H + 255) / 256, 256>>>(row);
    k_final<<<E_EDGES / 64, 256>>>(row, b1, b2, out);
}

// round 3
// speedup vs baseline: 2.2656x; 2.2656x over previous
#include <cuda_runtime.h>
#include <cstdint>
#include <math.h>

#define E_EDGES 640000
#define N_NODES 10000
#define D 128
#define H 4
#define NCOMB 1024
#define PHALF 512

// ---------------- scratch ---------------------------------------------------
__device__ __align__(16) float    g_Wcomb[NCOMB * D];            // tf32-rounded
__device__ __align__(16) float    g_W2T[D * D];
__device__ __align__(16) float    g_Y[(size_t)E_EDGES * PHALF];  // p-half (1.31 GB)
__device__ float    g_att[E_EDGES * H];
__device__ unsigned g_m[N_NODES * H];
__device__ float    g_s[N_NODES * H];

// ---------------- helpers ---------------------------------------------------
__device__ __forceinline__ uint32_t smem_u32(const void* p) {
    uint32_t a;
    asm("{ .reg .u64 t; cvta.to.shared.u64 t, %1; cvt.u32.u64 %0, t; }" : "=r"(a) : "l"(p));
    return a;
}
__device__ __forceinline__ uint32_t tf32r(float x) {
    uint32_t r; asm("cvt.rna.tf32.f32 %0, %1;" : "=r"(r) : "f"(x)); return r;
}
__device__ __forceinline__ void ldsm4(uint32_t* r, uint32_t addr) {
    asm volatile("ldmatrix.sync.aligned.m8n8.x4.shared.b16 {%0,%1,%2,%3}, [%4];"
                 : "=r"(r[0]), "=r"(r[1]), "=r"(r[2]), "=r"(r[3]) : "r"(addr));
}
__device__ __forceinline__ void mma_tf32(float* d, const uint32_t* a, const uint32_t* b) {
    asm volatile("mma.sync.aligned.m16n8k8.row.col.f32.tf32.tf32.f32 "
                 "{%0,%1,%2,%3}, {%4,%5,%6,%7}, {%8,%9}, {%0,%1,%2,%3};"
                 : "+f"(d[0]), "+f"(d[1]), "+f"(d[2]), "+f"(d[3])
                 : "r"(a[0]), "r"(a[1]), "r"(a[2]), "r"(a[3]), "r"(b[0]), "r"(b[1]));
}
#define CP_ASYNC16(dst, src) \
    asm volatile("cp.async.cg.shared.global [%0], [%1], 16;" :: "r"(dst), "l"(src))
#define CP_COMMIT() asm volatile("cp.async.commit_group;" ::: "memory")
#define CP_WAIT0()  asm volatile("cp.async.wait_group 0;" ::: "memory")

__device__ __forceinline__ unsigned encodeF(float x) {
    unsigned u = __float_as_uint(x);
    return (u & 0x80000000u) ? ~u : (u | 0x80000000u);
}
__device__ __forceinline__ float decodeF(unsigned e) {
    unsigned u = (e & 0x80000000u) ? (e ^ 0x80000000u) : ~e;
    return __uint_as_float(u);
}

// ---------------- K0: build weights (tf32-rounded Wcomb) + W2^T -------------
__global__ void k_build(const float* __restrict__ Wq, const float* __restrict__ Wk,
                        const float* __restrict__ Wv, const float* __restrict__ W1,
                        const float* __restrict__ W2) {
    int n = blockIdx.x;
    int f = threadIdx.x;
    if (n < NCOMB) {
        float acc = 0.f;
        if (n < H * D) {
            int h = n >> 7, g = n & 127;
            const float* wq = Wq + h * D * D;
            const float* wk = Wk + h * D * D;
            for (int d = 0; d < D; d++) acc += wq[d * D + f] * wk[d * D + g];
        } else {
            int m2 = n - H * D;
            int h = m2 >> 7, i = m2 & 127;
            const float* wv = Wv + h * D * D;
            for (int d = 0; d < D; d++) acc += W1[i * D + d] * wv[d * D + f];
        }
        g_Wcomb[n * D + f] = __uint_as_float(tf32r(acc));
    } else {
        int i = n - NCOMB;
        g_W2T[i * D + f] = W2[f * D + i];
    }
}

// ---------------- K1: reset segment buffers --------------------------------
__global__ void k_init() {
    int i = blockIdx.x * 256 + threadIdx.x;
    if (i < N_NODES * H) { g_m[i] = 0u; g_s[i] = 0.f; }
}

// ---------------- K2: tf32 mma.sync GEMM + fused att epilogue --------------
// smem: [0,512) attbuf(128 f), [1024, +64K) Zs, then Ws[2] (64K each)
// Tile layout in smem: row-major, row stride 512B, 16B chunks XOR-swizzled:
//   addr(row, k) = base + row*512 + (((k>>2) ^ (row&7))<<4) + (k&3)*4
#define SM_ATT 0
#define SM_Z   1024
#define SM_W0  (1024 + 65536)
#define SM_W1  (1024 + 131072)
#define SMEM_SZ (1024 + 196608)

__global__ void __launch_bounds__(256, 1) k_mma(const float* __restrict__ Z) {
    extern __shared__ char smem[];
    float* attbuf = (float*)(smem + SM_ATT);
    const int tid = threadIdx.x;
    const int lane = tid & 31, wid = tid >> 5;
    const int warpM = wid & 3, warpN = wid >> 2;
    const int m_base = warpM * 32, n_base = warpN * 64;
    const int e0 = blockIdx.x * 128;

    const uint32_t zbase = smem_u32(smem + SM_Z);
    const uint32_t wbase[2] = { smem_u32(smem + SM_W0), smem_u32(smem + SM_W1) };

    // ---- load Z tile (tf32-rounded, swizzled) ----
#pragma unroll
    for (int it = 0; it < 16; it++) {
        int i = it * 256 + tid;
        int row = i >> 5, c = i & 31;
        float4 v = *(const float4*)&Z[(size_t)(e0 + row) * D + c * 4];
        uint4 w = { tf32r(v.x), tf32r(v.y), tf32r(v.z), tf32r(v.w) };
        *(uint4*)(smem + SM_Z + row * 512 + (((uint32_t)c ^ (row & 7)) << 4)) = w;
    }

    // ---- prefetch W tile 0 ----
#pragma unroll
    for (int it = 0; it < 16; it++) {
        int i = it * 256 + tid;
        int row = i >> 5, c = i & 31;
        CP_ASYNC16(wbase[0] + row * 512 + (((uint32_t)c ^ (row & 7)) << 4),
                   &g_Wcomb[(size_t)row * D + c * 4]);
    }
    CP_COMMIT();

    // ldmatrix address components
    const int g8 = lane >> 3, l8 = lane & 7;
    // A: two m16 frags; tiles: (g8&1)->row+8, (g8>>1)->k chunk +1
    uint32_t arow[2], asw[2];
#pragma unroll
    for (int f = 0; f < 2; f++) {
        int r = m_base + f * 16 + (g8 & 1) * 8 + l8;
        arow[f] = (uint32_t)r * 512;
        asw[f] = (uint32_t)(r & 7);
    }
    const uint32_t ack = (uint32_t)(g8 >> 1);
    // B: four n16 groups; tiles: (g8>>1)->n row +8, (g8&1)->k chunk +1
    uint32_t brow[4], bsw[4];
#pragma unroll
    for (int q = 0; q < 4; q++) {
        int r = n_base + q * 16 + (g8 >> 1) * 8 + l8;
        brow[q] = (uint32_t)r * 512;
        bsw[q] = (uint32_t)(r & 7);
    }
    const uint32_t bck = (uint32_t)(g8 & 1);

    const int crow = m_base + (lane >> 2);     // c-frag row (f*16, +8 variants)
    const int ccol = n_base + (lane & 3) * 2;  // c-frag col (j*8 offset added)

    for (int nt = 0; nt < 8; nt++) {
        const int buf = nt & 1;
        CP_WAIT0();
        __syncthreads();
        if (nt < 7) {
#pragma unroll
            for (int it = 0; it < 16; it++) {
                int i = it * 256 + tid;
                int row = i >> 5, c = i & 31;
                CP_ASYNC16(wbase[buf ^ 1] + row * 512 + (((uint32_t)c ^ (row & 7)) << 4),
                           &g_Wcomb[(size_t)(nt + 1) * 128 * D + (size_t)row * D + c * 4]);
            }
            CP_COMMIT();
        }

        float acc[2][8][4];
#pragma unroll
        for (int f = 0; f < 2; f++)
#pragma unroll
            for (int j = 0; j < 8; j++)
#pragma unroll
                for (int r = 0; r < 4; r++) acc[f][j][r] = 0.f;

        const uint32_t wb = wbase[buf];
#pragma unroll
        for (int ks = 0; ks < 16; ks++) {
            const uint32_t kk = (uint32_t)(ks * 2);
            uint32_t afr[2][4];
#pragma unroll
            for (int f = 0; f < 2; f++)
                ldsm4(afr[f], zbase + arow[f] + (((kk + ack) ^ asw[f]) << 4));
            uint32_t bfr[8][2];
#pragma unroll
            for (int q = 0; q < 4; q++) {
                uint32_t t4[4];
                ldsm4(t4, wb + brow[q] + (((kk + bck) ^ bsw[q]) << 4));
                bfr[2 * q][0] = t4[0]; bfr[2 * q][1] = t4[1];
                bfr[2 * q + 1][0] = t4[2]; bfr[2 * q + 1][1] = t4[3];
            }
#pragma unroll
            for (int f = 0; f < 2; f++)
#pragma unroll
                for (int j = 0; j < 8; j++)
                    mma_tf32(acc[f][j], afr[f], bfr[j]);
        }

        if (nt < 4) {
            // ---- fused att epilogue ----
            if (tid < 128) attbuf[tid] = 0.f;
            __syncthreads();
            float part[2][2] = {{0.f, 0.f}, {0.f, 0.f}};
#pragma unroll
            for (int f = 0; f < 2; f++)
#pragma unroll
                for (int j = 0; j < 8; j++) {
                    int col = ccol + j * 8;           // feature index (0..127)
                    uint32_t coff = (((uint32_t)(col >> 2)) << 4) + (col & 3) * 4;
#pragma unroll
                    for (int r8 = 0; r8 < 2; r8++) {
                        int rr = crow + f * 16 + r8 * 8;
                        uint32_t sw = ((uint32_t)(rr & 7)) << 4;
                        float2 z = *(const float2*)(smem + SM_Z + rr * 512 + (coff ^ sw));
                        part[f][r8] += acc[f][j][r8 * 2] * z.x + acc[f][j][r8 * 2 + 1] * z.y;
                    }
                }
#pragma unroll
            for (int f = 0; f < 2; f++)
#pragma unroll
                for (int r8 = 0; r8 < 2; r8++) {
                    float p = part[f][r8];
                    p += __shfl_xor_sync(0xFFFFFFFFu, p, 1);
                    p += __shfl_xor_sync(0xFFFFFFFFu, p, 2);
                    if ((lane & 3) == 0)
                        atomicAdd(&attbuf[crow + f * 16 + r8 * 8], p);
                }
            __syncthreads();
            if (tid < 128)
                g_att[(size_t)(e0 + tid) * H + nt] = 0.08838834764831845f * attbuf[tid];
        } else {
            // ---- p-half store ----
            const int colb = (nt - 4) * 128 + ccol;
#pragma unroll
            for (int f = 0; f < 2; f++) {
                int r0 = crow + f * 16;
#pragma unroll
                for (int j = 0; j < 8; j++) {
                    *(float2*)&g_Y[(size_t)(e0 + r0) * PHALF + colb + j * 8] =
                        make_float2(acc[f][j][0], acc[f][j][1]);
                    *(float2*)&g_Y[(size_t)(e0 + r0 + 8) * PHALF + colb + j * 8] =
                        make_float2(acc[f][j][2], acc[f][j][3]);
                }
            }
        }
    }
}

// ---------------- K3: segment max ------------------------------------------
__global__ void k_max(const int* __restrict__ row) {
    int i = blockIdx.x * 256 + threadIdx.x;
    if (i >= E_EDGES * H) return;
    int e = i >> 2, h = i & 3;
    atomicMax(&g_m[row[e] * H + h], encodeF(g_att[i]));
}

// ---------------- K4: exp + segment sum ------------------------------------
__global__ void k_exp(const int* __restrict__ row) {
    int i = blockIdx.x * 256 + threadIdx.x;
    if (i >= E_EDGES * H) return;
    int e = i >> 2, h = i & 3;
    int rw = row[e];
    float m = decodeF(g_m[rw * H + h]);
    float ev = __expf(g_att[i] - m);
    g_att[i] = ev;
    atomicAdd(&g_s[rw * H + h], ev);
}

// ---------------- K5: w -> pre -> SiLU -> @W2^T -> out ---------------------
__global__ void __launch_bounds__(256) k_final(const int* __restrict__ row,
                                               const float* __restrict__ b1,
                                               const float* __restrict__ b2,
                                               float* __restrict__ out) {
    __shared__ float ws[64][4];
    __shared__ float h1c[64][33];
    __shared__ float W2c[32][128];
    const int e0 = blockIdx.x * 64;
    const int tid = threadIdx.x;

    {
        int m = tid >> 2, h = tid & 3;
        int e = e0 + m;
        int rw = row[e];
        ws[m][h] = g_att[e * H + h] / g_s[rw * H + h];
    }

    const int tx = tid & 15, ty = tid >> 4;
    const int n0 = tx * 8, m0 = ty * 4;
    float acc[4][8];
#pragma unroll
    for (int i = 0; i < 4; i++)
#pragma unroll
        for (int j = 0; j < 8; j++) acc[i][j] = 0.f;

    for (int kt = 0; kt < 4; kt++) {
        __syncthreads();
#pragma unroll
        for (int r = 0; r < 8; r++) {
            int idx = r * 256 + tid;
            int m = idx >> 5, ic = idx & 31;
            int i = kt * 32 + ic;
            const float* yp = g_Y + (size_t)(e0 + m) * PHALF + i;
            float pre = b1[i];
#pragma unroll
            for (int h = 0; h < H; h++) pre += ws[m][h] * yp[h * 128];
            h1c[m][ic] = pre / (1.f + __expf(-pre));
        }
#pragma unroll
        for (int p = 0; p < 4; p++) {
            int r = (tid >> 5) + p * 8;
            int c = (tid & 31) * 4;
            float4 v = *(const float4*)&g_W2T[(kt * 32 + r) * D + c];
            *(float4*)&W2c[r][c] = v;
        }
        __syncthreads();
#pragma unroll
        for (int k = 0; k < 32; k++) {
            float a[4];
#pragma unroll
            for (int mi = 0; mi < 4; mi++) a[mi] = h1c[m0 + mi][k];
            float4 bv0 = *(const float4*)&W2c[k][n0];
            float4 bv1 = *(const float4*)&W2c[k][n0 + 4];
            float b[8] = {bv0.x, bv0.y, bv0.z, bv0.w, bv1.x, bv1.y, bv1.z, bv1.w};
#pragma unroll
            for (int mi = 0; mi < 4; mi++)
#pragma unroll
                for (int j = 0; j < 8; j++) acc[mi][j] += a[mi] * b[j];
        }
    }
    float bb[8];
#pragma unroll
    for (int j = 0; j < 8; j++) bb[j] = b2[n0 + j];
#pragma unroll
    for (int mi = 0; mi < 4; mi++) {
        int e = e0 + m0 + mi;
        float4 o0 = make_float4(acc[mi][0] + bb[0], acc[mi][1] + bb[1],
                                acc[mi][2] + bb[2], acc[mi][3] + bb[3]);
        float4 o1 = make_float4(acc[mi][4] + bb[4], acc[mi][5] + bb[5],
                                acc[mi][6] + bb[6], acc[mi][7] + bb[7]);
        *(float4*)&out[(size_t)e * D + n0] = o0;
        *(float4*)&out[(size_t)e * D + n0 + 4] = o1;
    }
}

// ---------------- launch ----------------------------------------------------
extern "C" void kernel_launch(void* const* d_in, const int* in_sizes, int n_in,
                              void* d_out, int out_size) {
    const float* Z     = (const float*)d_in[0];
    const int*   edges = (const int*)  d_in[1];
    const float* Wq    = (const float*)d_in[2];
    const float* Wk    = (const float*)d_in[3];
    const float* Wv    = (const float*)d_in[4];
    const float* W1    = (const float*)d_in[5];
    const float* b1    = (const float*)d_in[6];
    const float* W2    = (const float*)d_in[7];
    const float* b2    = (const float*)d_in[8];
    float* out = (float*)d_out;
    const int* row = edges;

    cudaFuncSetAttribute(k_mma, cudaFuncAttributeMaxDynamicSharedMemorySize, SMEM_SZ);

    k_build<<<NCOMB + D, D>>>(Wq, Wk, Wv, W1, W2);
    k_init<<<(N_NODES * H + 255) / 256, 256>>>();
    k_mma<<<E_EDGES / 128, 256, SMEM_SZ>>>(Z);
    k_max<<<(E_EDGES * H + 255) / 256, 256>>>(row);
    k_exp<<<(E_EDGES * H + 255) / 256, 256>>>(row);
    k_final<<<E_EDGES / 64, 256>>>(row, b1, b2, out);
}